// round 9
// baseline (speedup 1.0000x reference)
#include <cuda_runtime.h>
#include <cuda_fp16.h>

#define NFLAT 1056768   /* 32*256*129 */
#define PLANE_F 33024   /* 256*129 */
#define PIX 2097152     /* 32*256*256 per (b,c) plane */
#define NREAL 25165824  /* 12 * PIX */
#define PACK_BLOCKS 24576  /* NREAL/4/256 */
#define H_BLOCKS 480       /* 15 (c,k2) x 32 i0 */

__device__ float2  d_H[8192 * 15];   // [i0*256+i1][c*5+k2]
__device__ __half2 d_pairs[NREAL];   // staggered x-pairs: (v[x], v[x+1 clamped])

__device__ __forceinline__ unsigned pk2(float a, float b) {
    __half2 h = __floats2half2_rn(a, b);
    return *reinterpret_cast<unsigned*>(&h);
}

// Blocks [0, H_BLOCKS): fold the sparse spectrum directly into per-row H
// (compute-bound, overlaps the DRAM-bound pack blocks that follow).
// Blocks [H_BLOCKS, H_BLOCKS+PACK_BLOCKS): pack fr into staggered half2 pairs.
__global__ void __launch_bounds__(256) pack_h_kernel(
        const float* __restrict__ fr,
        const float* __restrict__ seeds,
        const float* __restrict__ Pk,
        const float* __restrict__ defscale,
        const int*  __restrict__ feed_idx,
        int fdim) {
    if (blockIdx.x < H_BLOCKS) {
        int ex = blockIdx.x;
        int ck = ex >> 5;            // 0..14 = c*5+k2
        int i0 = ex & 31;
        int i1 = threadIdx.x;
        int c  = ck / 5, k2 = ck - c * 5;
        float dsc = __ldg(defscale + c);
        const float inv_n = 1.0f / 2097152.0f;    // irfftn normalization
        float ax = 0.f, ay = 0.f;
        for (int j = 0; j < fdim; j++) {
            int flat = __ldg(feed_idx + j);
            int part = flat / NFLAT;              // 0 = re, 1 = im
            int r = flat - part * NFLAT;
            int k0 = r / PLANE_F; r -= k0 * PLANE_F;
            int k1 = r / 129;
            int k2e = r - k1 * 129;
            if (k2e != k2) continue;              // uniform branch (j uniform)
            int f0 = (k0 <= 16) ? k0 : k0 - 32;   // |f0| <= 4 (ksq<=16)
            int f1 = (k1 <= 128) ? k1 : k1 - 256;
            float w = (k0 == 0 && k1 == 0 && k2e == 0) ? 1.0f : 2.0f;
            float v = __ldg(Pk + j) * w * inv_n * __ldg(seeds + c * fdim + j) * dsc;
            float ph = (float)(8 * f0 * i0 + f1 * i1) * (1.0f / 128.0f);
            float sn, cs;
            sincospif(ph, &sn, &cs);
            if (part == 0) { ax += v * cs; ay += v * sn; }   // re * e^{i t}
            else           { ax -= v * sn; ay += v * cs; }   // i*im * e^{i t}
        }
        d_H[(i0 * 256 + i1) * 15 + ck] = make_float2(ax, ay);
    } else {
        int i = ((blockIdx.x - H_BLOCKS) * 256 + threadIdx.x) * 4;  // i%256 in {0,4,..,252}
        float4 f = __ldcs(reinterpret_cast<const float4*>(fr + i));
        float s = __ldcs(fr + min(i + 4, NREAL - 1));
        int pos = i & 255;
        float n3 = (pos == 252) ? f.w : s;        // clamp pair at row end
        uint4 u;
        u.x = pk2(f.x, f.y);
        u.y = pk2(f.y, f.z);
        u.z = pk2(f.z, f.w);
        u.w = pk2(f.w, n3);
        *reinterpret_cast<uint4*>(reinterpret_cast<unsigned*>(d_pairs) + i) = u;
    }
}

// Barrier-free, smem-free deform: read 15 uniform H values, build k2 twiddle
// powers by complex multiplication, evaluate disp, gather, store.
__global__ void __launch_bounds__(256) deform_kernel(float* __restrict__ out) {
    int i2 = threadIdx.x;
    int i1 = blockIdx.x;
    int i0 = blockIdx.y;

    const float2* Hp = d_H + (i0 * 256 + i1) * 15;
    float2 h[15];
    #pragma unroll
    for (int j = 0; j < 15; j++) h[j] = __ldg(Hp + j);

    float s1, c1;
    sincospif((float)i2 * (1.0f / 128.0f), &s1, &c1);
    float2 w1 = make_float2(c1, s1);
    float2 w2 = make_float2(c1 * c1 - s1 * s1, 2.f * c1 * s1);
    float2 w3 = make_float2(w2.x * w1.x - w2.y * w1.y, w2.x * w1.y + w2.y * w1.x);
    float2 w4 = make_float2(w2.x * w2.x - w2.y * w2.y, 2.f * w2.x * w2.y);

    float dd[3];
    #pragma unroll
    for (int c = 0; c < 3; c++) {
        const float2* hb = h + c * 5;
        float acc = hb[0].x;                       // k2=0: w=(1,0)
        acc += hb[1].x * w1.x - hb[1].y * w1.y;
        acc += hb[2].x * w2.x - hb[2].y * w2.y;
        acc += hb[3].x * w3.x - hb[3].y * w3.y;
        acc += hb[4].x * w4.x - hb[4].y * w4.y;
        dd[c] = acc;
    }

    // grid_sample: bilinear, border clamp, align_corners=True -> sample at i - disp
    float fz = fminf(fmaxf((float)i0 - dd[0], 0.f), 31.f);
    float fy = fminf(fmaxf((float)i1 - dd[1], 0.f), 255.f);
    float fx = fminf(fmaxf((float)i2 - dd[2], 0.f), 255.f);
    int z0 = (int)fz, y0 = (int)fy, x0 = (int)fx;
    float wz = fz - (float)z0, wy = fy - (float)y0, wx = fx - (float)x0;
    int z1 = min(z0 + 1, 31), y1 = min(y0 + 1, 255);

    // pair buffer already encodes the x1 = min(x0+1,255) clamp
    int q00 = z0 * 65536 + y0 * 256 + x0;
    int q01 = z0 * 65536 + y1 * 256 + x0;
    int q10 = z1 * 65536 + y0 * 256 + x0;
    int q11 = z1 * 65536 + y1 * 256 + x0;
    int pix = i0 * 65536 + i1 * 256 + i2;

    float iwx = 1.f - wx, iwy = 1.f - wy, iwz = 1.f - wz;

    __half2 v[48];
    #pragma unroll
    for (int bc = 0; bc < 12; bc++) {
        const __half2* p = d_pairs + (size_t)bc * PIX;
        v[bc*4+0] = __ldg(p + q00);
        v[bc*4+1] = __ldg(p + q01);
        v[bc*4+2] = __ldg(p + q10);
        v[bc*4+3] = __ldg(p + q11);
    }
    #pragma unroll
    for (int bc = 0; bc < 12; bc++) {
        float2 v00 = __half22float2(v[bc*4+0]);
        float2 v01 = __half22float2(v[bc*4+1]);
        float2 v10 = __half22float2(v[bc*4+2]);
        float2 v11 = __half22float2(v[bc*4+3]);
        float c00 = v00.x * iwx + v00.y * wx;
        float c01 = v01.x * iwx + v01.y * wx;
        float c10 = v10.x * iwx + v10.y * wx;
        float c11 = v11.x * iwx + v11.y * wx;
        float c0 = c00 * iwy + c01 * wy;
        float c1 = c10 * iwy + c11 * wy;
        __stcs(out + (size_t)bc * PIX + pix, c0 * iwz + c1 * wz);
    }
}

extern "C" void kernel_launch(void* const* d_in, const int* in_sizes, int n_in,
                              void* d_out, int out_size) {
    const float* fr       = (const float*)d_in[0];
    const float* seeds    = (const float*)d_in[1];
    const float* Pk       = (const float*)d_in[2];
    const float* defscale = (const float*)d_in[3];
    const int*   feed_idx = (const int*)d_in[5];
    int fdim = in_sizes[5];

    pack_h_kernel<<<H_BLOCKS + PACK_BLOCKS, 256>>>(fr, seeds, Pk, defscale, feed_idx, fdim);
    dim3 g(256, 32);
    deform_kernel<<<g, 256>>>((float*)d_out);
}

// round 11
// speedup vs baseline: 1.1085x; 1.1085x over previous
#include <cuda_runtime.h>
#include <cuda_fp16.h>

#define NFLAT 1056768   /* 32*256*129 */
#define PLANE_F 33024   /* 256*129 */
#define PIX 2097152     /* 32*256*256 per (b,c) plane */
#define NREAL 25165824  /* 12 * PIX */
#define PACK_BLOCKS 24576  /* NREAL/4/256 */
#define H_BLOCKS 480       /* 15 (c,k2) x 32 i0 */

__device__ float2  d_H[8192 * 15];   // [i0*256+i1][c*5+k2]
__device__ __half2 d_pairs[NREAL];   // staggered x-pairs: (v[x], v[x+1 clamped])

__device__ __forceinline__ unsigned pk2(float a, float b) {
    __half2 h = __floats2half2_rn(a, b);
    return *reinterpret_cast<unsigned*>(&h);
}

// Blocks [0, H_BLOCKS): fold the sparse spectrum into per-row H using a smem
// twiddle table (1 LDS + 4 FMA per feed entry, no per-iteration sincos).
// Blocks [H_BLOCKS, ...): pack fr into staggered half2 pairs (DRAM-bound).
__global__ void __launch_bounds__(256) pack_h_kernel(
        const float* __restrict__ fr,
        const float* __restrict__ seeds,
        const float* __restrict__ Pk,
        const float* __restrict__ defscale,
        const int*  __restrict__ feed_idx,
        int fdim) {
    if (blockIdx.x < H_BLOCKS) {
        __shared__ float2 sW[256];
        int tid = threadIdx.x;
        {
            float sn, cs;
            sincospif((float)tid * (1.0f / 128.0f), &sn, &cs);
            sW[tid] = make_float2(cs, sn);
        }
        __syncthreads();
        int ex = blockIdx.x;
        int ck = ex >> 5;            // 0..14 = c*5+k2
        int i0 = ex & 31;
        int i1 = tid;
        int c  = ck / 5, k2 = ck - c * 5;
        float dsc = __ldg(defscale + c);
        const float inv_n = 1.0f / 2097152.0f;    // irfftn normalization
        float ax = 0.f, ay = 0.f;
        for (int j = 0; j < fdim; j++) {
            int flat = __ldg(feed_idx + j);
            int part = flat / NFLAT;              // 0 = re, 1 = im
            int r = flat - part * NFLAT;
            int k0 = r / PLANE_F; r -= k0 * PLANE_F;
            int k1 = r / 129;
            int k2e = r - k1 * 129;
            if (k2e != k2) continue;              // uniform branch (j uniform)
            int f0 = (k0 <= 16) ? k0 : k0 - 32;   // |f0| <= 4 (ksq<=16)
            int f1 = (k1 <= 128) ? k1 : k1 - 256;
            float w = (k0 == 0 && k1 == 0 && k2e == 0) ? 1.0f : 2.0f;
            float v = __ldg(Pk + j) * w * inv_n * __ldg(seeds + c * fdim + j) * dsc;
            int tt = (8 * f0 * i0 + f1 * i1 + 8192) & 255;
            float2 wv = sW[tt];
            if (part == 0) { ax += v * wv.x; ay += v * wv.y; }   // re * e^{i t}
            else           { ax -= v * wv.y; ay += v * wv.x; }   // i*im * e^{i t}
        }
        d_H[(i0 * 256 + i1) * 15 + ck] = make_float2(ax, ay);
    } else {
        int i = ((blockIdx.x - H_BLOCKS) * 256 + threadIdx.x) * 4;  // i%256 in {0,4,..,252}
        float4 f = __ldcs(reinterpret_cast<const float4*>(fr + i));
        float s = __ldcs(fr + min(i + 4, NREAL - 1));
        int pos = i & 255;
        float n3 = (pos == 252) ? f.w : s;        // clamp pair at row end
        uint4 u;
        u.x = pk2(f.x, f.y);
        u.y = pk2(f.y, f.z);
        u.z = pk2(f.z, f.w);
        u.w = pk2(f.w, n3);
        *reinterpret_cast<uint4*>(reinterpret_cast<unsigned*>(d_pairs) + i) = u;
    }
}

// Barrier-free, smem-free deform: read 15 uniform H values, build k2 twiddle
// powers by complex multiplication, evaluate disp, gather, store.
__global__ void __launch_bounds__(256) deform_kernel(float* __restrict__ out) {
    int i2 = threadIdx.x;
    int i1 = blockIdx.x;
    int i0 = blockIdx.y;

    const float2* Hp = d_H + (i0 * 256 + i1) * 15;
    float2 h[15];
    #pragma unroll
    for (int j = 0; j < 15; j++) h[j] = __ldg(Hp + j);

    float s1, c1;
    sincospif((float)i2 * (1.0f / 128.0f), &s1, &c1);
    float2 w1 = make_float2(c1, s1);
    float2 w2 = make_float2(c1 * c1 - s1 * s1, 2.f * c1 * s1);
    float2 w3 = make_float2(w2.x * w1.x - w2.y * w1.y, w2.x * w1.y + w2.y * w1.x);
    float2 w4 = make_float2(w2.x * w2.x - w2.y * w2.y, 2.f * w2.x * w2.y);

    float dd[3];
    #pragma unroll
    for (int c = 0; c < 3; c++) {
        const float2* hb = h + c * 5;
        float acc = hb[0].x;                       // k2=0: w=(1,0)
        acc += hb[1].x * w1.x - hb[1].y * w1.y;
        acc += hb[2].x * w2.x - hb[2].y * w2.y;
        acc += hb[3].x * w3.x - hb[3].y * w3.y;
        acc += hb[4].x * w4.x - hb[4].y * w4.y;
        dd[c] = acc;
    }

    // grid_sample: bilinear, border clamp, align_corners=True -> sample at i - disp
    float fz = fminf(fmaxf((float)i0 - dd[0], 0.f), 31.f);
    float fy = fminf(fmaxf((float)i1 - dd[1], 0.f), 255.f);
    float fx = fminf(fmaxf((float)i2 - dd[2], 0.f), 255.f);
    int z0 = (int)fz, y0 = (int)fy, x0 = (int)fx;
    float wz = fz - (float)z0, wy = fy - (float)y0, wx = fx - (float)x0;
    int z1 = min(z0 + 1, 31), y1 = min(y0 + 1, 255);

    // pair buffer already encodes the x1 = min(x0+1,255) clamp
    int q00 = z0 * 65536 + y0 * 256 + x0;
    int q01 = z0 * 65536 + y1 * 256 + x0;
    int q10 = z1 * 65536 + y0 * 256 + x0;
    int q11 = z1 * 65536 + y1 * 256 + x0;
    int pix = i0 * 65536 + i1 * 256 + i2;

    float iwx = 1.f - wx, iwy = 1.f - wy, iwz = 1.f - wz;

    __half2 v[48];
    #pragma unroll
    for (int bc = 0; bc < 12; bc++) {
        const __half2* p = d_pairs + (size_t)bc * PIX;
        v[bc*4+0] = __ldg(p + q00);
        v[bc*4+1] = __ldg(p + q01);
        v[bc*4+2] = __ldg(p + q10);
        v[bc*4+3] = __ldg(p + q11);
    }
    #pragma unroll
    for (int bc = 0; bc < 12; bc++) {
        float2 v00 = __half22float2(v[bc*4+0]);
        float2 v01 = __half22float2(v[bc*4+1]);
        float2 v10 = __half22float2(v[bc*4+2]);
        float2 v11 = __half22float2(v[bc*4+3]);
        float c00 = v00.x * iwx + v00.y * wx;
        float c01 = v01.x * iwx + v01.y * wx;
        float c10 = v10.x * iwx + v10.y * wx;
        float c11 = v11.x * iwx + v11.y * wx;
        float c0 = c00 * iwy + c01 * wy;
        float c1 = c10 * iwy + c11 * wy;
        __stcs(out + (size_t)bc * PIX + pix, c0 * iwz + c1 * wz);
    }
}

extern "C" void kernel_launch(void* const* d_in, const int* in_sizes, int n_in,
                              void* d_out, int out_size) {
    const float* fr       = (const float*)d_in[0];
    const float* seeds    = (const float*)d_in[1];
    const float* Pk       = (const float*)d_in[2];
    const float* defscale = (const float*)d_in[3];
    const int*   feed_idx = (const int*)d_in[5];
    int fdim = in_sizes[5];

    pack_h_kernel<<<H_BLOCKS + PACK_BLOCKS, 256>>>(fr, seeds, Pk, defscale, feed_idx, fdim);
    dim3 g(256, 32);
    deform_kernel<<<g, 256>>>((float*)d_out);
}

// round 12
// speedup vs baseline: 1.1293x; 1.0188x over previous
#include <cuda_runtime.h>
#include <cuda_fp16.h>

#define NFLAT 1056768   /* 32*256*129 */
#define PLANE_F 33024   /* 256*129 */
#define PIX 2097152     /* 32*256*256 per (b,c) plane */
#define NREAL 25165824  /* 12 * PIX */
#define PACK_BLOCKS 24576  /* NREAL/4/256 */
#define H_BLOCKS 480       /* 15 (c,k2) x 32 i0 */
#define CHUNK 512

__device__ float2  d_H[8192 * 15];   // [i0*256+i1][c*5+k2]
__device__ __half2 d_pairs[NREAL];   // staggered x-pairs: (v[x], v[x+1 clamped])

__device__ __forceinline__ unsigned pk2(float a, float b) {
    __half2 h = __floats2half2_rn(a, b);
    return *reinterpret_cast<unsigned*>(&h);
}

// Blocks [0, H_BLOCKS): fold the sparse spectrum into per-row H.
// Feed is staged+predecoded into smem in parallel (one latency exposure per
// chunk), so the serial fold loop is pure LDS+FMA (~8 ops/entry).
// Blocks [H_BLOCKS, ...): pack fr into staggered half2 pairs (DRAM-bound).
__global__ void __launch_bounds__(256) pack_h_kernel(
        const float* __restrict__ fr,
        const float* __restrict__ seeds,
        const float* __restrict__ Pk,
        const float* __restrict__ defscale,
        const int*  __restrict__ feed_idx,
        int fdim) {
    if (blockIdx.x < H_BLOCKS) {
        __shared__ float2 sW[256];
        __shared__ float sV[CHUNK];
        __shared__ int   sM[CHUNK];
        int tid = threadIdx.x;
        {
            float sn, cs;
            sincospif((float)tid * (1.0f / 128.0f), &sn, &cs);
            sW[tid] = make_float2(cs, sn);
        }
        int ex = blockIdx.x;
        int ck = ex >> 5;            // 0..14 = c*5+k2
        int i0 = ex & 31;
        int i1 = tid;
        int c  = ck / 5, k2 = ck - c * 5;
        float dsc = __ldg(defscale + c);
        const float inv_n = 1.0f / 2097152.0f;    // irfftn normalization
        float ax = 0.f, ay = 0.f;

        for (int base = 0; base < fdim; base += CHUNK) {
            int len = min(CHUNK, fdim - base);
            __syncthreads();
            // parallel stage + predecode (2 chunks' worth handled by 256 threads)
            for (int t = tid; t < len; t += 256) {
                int j = base + t;
                int flat = __ldg(feed_idx + j);
                int part = flat / NFLAT;              // 0 = re, 1 = im
                int r = flat - part * NFLAT;
                int k0 = r / PLANE_F; r -= k0 * PLANE_F;
                int k1 = r / 129;
                int k2e = r - k1 * 129;
                int f0 = (k0 <= 16) ? k0 : k0 - 32;   // |f0| <= 4 (ksq<=16)
                int f1 = (k1 <= 128) ? k1 : k1 - 256; // |f1| <= 4
                float w = (k0 == 0 && k1 == 0 && k2e == 0) ? 1.0f : 2.0f;
                float v = __ldg(Pk + j) * w * inv_n
                        * __ldg(seeds + c * fdim + j) * dsc;
                // part=1 (i * e^{it}) == phase rotation by +64/256 turn
                int tb = (8 * f0 * i0 + 64 * part + 8192) & 255;
                sV[t] = (k2e == k2) ? v : 0.0f;       // mask wrong-k2 entries
                sM[t] = (tb << 8) | (f1 + 4);
            }
            __syncthreads();
            for (int t = 0; t < len; t++) {
                int m = sM[t];
                float v = sV[t];
                int tt = ((m >> 8) + ((m & 15) - 4) * i1) & 255;
                float2 wv = sW[tt];
                ax += v * wv.x;
                ay += v * wv.y;
            }
        }
        d_H[(i0 * 256 + i1) * 15 + ck] = make_float2(ax, ay);
    } else {
        int i = ((blockIdx.x - H_BLOCKS) * 256 + threadIdx.x) * 4;  // i%256 in {0,4,..,252}
        float4 f = __ldcs(reinterpret_cast<const float4*>(fr + i));
        float s = __ldcs(fr + min(i + 4, NREAL - 1));
        int pos = i & 255;
        float n3 = (pos == 252) ? f.w : s;        // clamp pair at row end
        uint4 u;
        u.x = pk2(f.x, f.y);
        u.y = pk2(f.y, f.z);
        u.z = pk2(f.z, f.w);
        u.w = pk2(f.w, n3);
        *reinterpret_cast<uint4*>(reinterpret_cast<unsigned*>(d_pairs) + i) = u;
    }
}

// Barrier-free, smem-free deform: read 15 uniform H values, build k2 twiddle
// powers by complex multiplication, evaluate disp, gather, store.
__global__ void __launch_bounds__(256) deform_kernel(float* __restrict__ out) {
    int i2 = threadIdx.x;
    int i1 = blockIdx.x;
    int i0 = blockIdx.y;

    const float2* Hp = d_H + (i0 * 256 + i1) * 15;
    float2 h[15];
    #pragma unroll
    for (int j = 0; j < 15; j++) h[j] = __ldg(Hp + j);

    float s1, c1;
    sincospif((float)i2 * (1.0f / 128.0f), &s1, &c1);
    float2 w1 = make_float2(c1, s1);
    float2 w2 = make_float2(c1 * c1 - s1 * s1, 2.f * c1 * s1);
    float2 w3 = make_float2(w2.x * w1.x - w2.y * w1.y, w2.x * w1.y + w2.y * w1.x);
    float2 w4 = make_float2(w2.x * w2.x - w2.y * w2.y, 2.f * w2.x * w2.y);

    float dd[3];
    #pragma unroll
    for (int c = 0; c < 3; c++) {
        const float2* hb = h + c * 5;
        float acc = hb[0].x;                       // k2=0: w=(1,0)
        acc += hb[1].x * w1.x - hb[1].y * w1.y;
        acc += hb[2].x * w2.x - hb[2].y * w2.y;
        acc += hb[3].x * w3.x - hb[3].y * w3.y;
        acc += hb[4].x * w4.x - hb[4].y * w4.y;
        dd[c] = acc;
    }

    // grid_sample: bilinear, border clamp, align_corners=True -> sample at i - disp
    float fz = fminf(fmaxf((float)i0 - dd[0], 0.f), 31.f);
    float fy = fminf(fmaxf((float)i1 - dd[1], 0.f), 255.f);
    float fx = fminf(fmaxf((float)i2 - dd[2], 0.f), 255.f);
    int z0 = (int)fz, y0 = (int)fy, x0 = (int)fx;
    float wz = fz - (float)z0, wy = fy - (float)y0, wx = fx - (float)x0;
    int z1 = min(z0 + 1, 31), y1 = min(y0 + 1, 255);

    // pair buffer already encodes the x1 = min(x0+1,255) clamp
    int q00 = z0 * 65536 + y0 * 256 + x0;
    int q01 = z0 * 65536 + y1 * 256 + x0;
    int q10 = z1 * 65536 + y0 * 256 + x0;
    int q11 = z1 * 65536 + y1 * 256 + x0;
    int pix = i0 * 65536 + i1 * 256 + i2;

    float iwx = 1.f - wx, iwy = 1.f - wy, iwz = 1.f - wz;

    __half2 v[48];
    #pragma unroll
    for (int bc = 0; bc < 12; bc++) {
        const __half2* p = d_pairs + (size_t)bc * PIX;
        v[bc*4+0] = __ldg(p + q00);
        v[bc*4+1] = __ldg(p + q01);
        v[bc*4+2] = __ldg(p + q10);
        v[bc*4+3] = __ldg(p + q11);
    }
    #pragma unroll
    for (int bc = 0; bc < 12; bc++) {
        float2 v00 = __half22float2(v[bc*4+0]);
        float2 v01 = __half22float2(v[bc*4+1]);
        float2 v10 = __half22float2(v[bc*4+2]);
        float2 v11 = __half22float2(v[bc*4+3]);
        float c00 = v00.x * iwx + v00.y * wx;
        float c01 = v01.x * iwx + v01.y * wx;
        float c10 = v10.x * iwx + v10.y * wx;
        float c11 = v11.x * iwx + v11.y * wx;
        float c0 = c00 * iwy + c01 * wy;
        float c1 = c10 * iwy + c11 * wy;
        __stcs(out + (size_t)bc * PIX + pix, c0 * iwz + c1 * wz);
    }
}

extern "C" void kernel_launch(void* const* d_in, const int* in_sizes, int n_in,
                              void* d_out, int out_size) {
    const float* fr       = (const float*)d_in[0];
    const float* seeds    = (const float*)d_in[1];
    const float* Pk       = (const float*)d_in[2];
    const float* defscale = (const float*)d_in[3];
    const int*   feed_idx = (const int*)d_in[5];
    int fdim = in_sizes[5];

    pack_h_kernel<<<H_BLOCKS + PACK_BLOCKS, 256>>>(fr, seeds, Pk, defscale, feed_idx, fdim);
    dim3 g(256, 32);
    deform_kernel<<<g, 256>>>((float*)d_out);
}

// round 14
// speedup vs baseline: 1.3090x; 1.1591x over previous
#include <cuda_runtime.h>
#include <cuda_fp16.h>

#define NFLAT 1056768   /* 32*256*129 */
#define PLANE_F 33024   /* 256*129 */
#define PIX 2097152     /* 32*256*256 per (b,c) plane */
#define NREAL 25165824  /* 12 * PIX */
#define NPAIR 6         /* plane pairs */
#define PACK_BLOCKS 12288  /* NPAIR*PIX/4/256 */
#define H_BLOCKS 480       /* 15 (c,k2) x 32 i0 */
#define CHUNK 512

__device__ float2  d_H[8192 * 15];     // [i0*256+i1][c*5+k2]
__device__ uint2   d_quads[NPAIR * PIX]; // (pa[x],pa[x+1],pb[x],pb[x+1]) fp16 quads

__device__ __forceinline__ unsigned pk2(float a, float b) {
    __half2 h = __floats2half2_rn(a, b);
    return *reinterpret_cast<unsigned*>(&h);
}

// Blocks [0, H_BLOCKS): fold sparse spectrum into per-row H (staged feed).
// Blocks [H_BLOCKS, ...): pack fr plane-pairs into staggered fp16 quads.
__global__ void __launch_bounds__(256) pack_h_kernel(
        const float* __restrict__ fr,
        const float* __restrict__ seeds,
        const float* __restrict__ Pk,
        const float* __restrict__ defscale,
        const int*  __restrict__ feed_idx,
        int fdim) {
    if (blockIdx.x < H_BLOCKS) {
        __shared__ float2 sW[256];
        __shared__ float sV[CHUNK];
        __shared__ int   sM[CHUNK];
        int tid = threadIdx.x;
        {
            float sn, cs;
            sincospif((float)tid * (1.0f / 128.0f), &sn, &cs);
            sW[tid] = make_float2(cs, sn);
        }
        int ex = blockIdx.x;
        int ck = ex >> 5;            // 0..14 = c*5+k2
        int i0 = ex & 31;
        int i1 = tid;
        int c  = ck / 5, k2 = ck - c * 5;
        float dsc = __ldg(defscale + c);
        const float inv_n = 1.0f / 2097152.0f;    // irfftn normalization
        float ax = 0.f, ay = 0.f;

        for (int base = 0; base < fdim; base += CHUNK) {
            int len = min(CHUNK, fdim - base);
            __syncthreads();
            for (int t = tid; t < len; t += 256) {
                int j = base + t;
                int flat = __ldg(feed_idx + j);
                int part = flat / NFLAT;              // 0 = re, 1 = im
                int r = flat - part * NFLAT;
                int k0 = r / PLANE_F; r -= k0 * PLANE_F;
                int k1 = r / 129;
                int k2e = r - k1 * 129;
                int f0 = (k0 <= 16) ? k0 : k0 - 32;   // |f0| <= 4 (ksq<=16)
                int f1 = (k1 <= 128) ? k1 : k1 - 256; // |f1| <= 4
                float w = (k0 == 0 && k1 == 0 && k2e == 0) ? 1.0f : 2.0f;
                float v = __ldg(Pk + j) * w * inv_n
                        * __ldg(seeds + c * fdim + j) * dsc;
                // part=1 (i * e^{it}) == phase rotation by +64/256 turn
                int tb = (8 * f0 * i0 + 64 * part + 8192) & 255;
                sV[t] = (k2e == k2) ? v : 0.0f;       // mask wrong-k2 entries
                sM[t] = (tb << 8) | (f1 + 4);
            }
            __syncthreads();
            for (int t = 0; t < len; t++) {
                int m = sM[t];
                float v = sV[t];
                int tt = ((m >> 8) + ((m & 15) - 4) * i1) & 255;
                float2 wv = sW[tt];
                ax += v * wv.x;
                ay += v * wv.y;
            }
        }
        d_H[(i0 * 256 + i1) * 15 + ck] = make_float2(ax, ay);
    } else {
        int t = (blockIdx.x - H_BLOCKS) * 256 + threadIdx.x;
        int i = t * 4;                       // pixel index within pair plane * 4
        int g = i >> 21;                     // pair id (PIX = 2^21)
        int pix = i & (PIX - 1);
        const float* pa = fr + (size_t)(2 * g) * PIX;
        const float* pb = pa + PIX;
        float4 fa = __ldcs(reinterpret_cast<const float4*>(pa + pix));
        float4 fb = __ldcs(reinterpret_cast<const float4*>(pb + pix));
        int nn = min(pix + 4, PIX - 1);
        float sa = __ldcs(pa + nn);
        float sb = __ldcs(pb + nn);
        int pos = pix & 255;
        float na = (pos == 252) ? fa.w : sa;   // clamp pair at row end (x=255)
        float nb = (pos == 252) ? fb.w : sb;
        uint4 u0, u1;
        u0.x = pk2(fa.x, fa.y); u0.y = pk2(fb.x, fb.y);
        u0.z = pk2(fa.y, fa.z); u0.w = pk2(fb.y, fb.z);
        u1.x = pk2(fa.z, fa.w); u1.y = pk2(fb.z, fb.w);
        u1.z = pk2(fa.w, na);   u1.w = pk2(fb.w, nb);
        uint4* dst = reinterpret_cast<uint4*>(d_quads + ((size_t)g << 21) + pix);
        dst[0] = u0;
        dst[1] = u1;
    }
}

// Barrier-free, smem-free deform: uniform H -> disp -> 24 LDG.64 quad gathers.
__global__ void __launch_bounds__(256) deform_kernel(float* __restrict__ out) {
    int i2 = threadIdx.x;
    int i1 = blockIdx.x;
    int i0 = blockIdx.y;

    const float2* Hp = d_H + (i0 * 256 + i1) * 15;
    float2 h[15];
    #pragma unroll
    for (int j = 0; j < 15; j++) h[j] = __ldg(Hp + j);

    float s1, c1;
    sincospif((float)i2 * (1.0f / 128.0f), &s1, &c1);
    float2 w1 = make_float2(c1, s1);
    float2 w2 = make_float2(c1 * c1 - s1 * s1, 2.f * c1 * s1);
    float2 w3 = make_float2(w2.x * w1.x - w2.y * w1.y, w2.x * w1.y + w2.y * w1.x);
    float2 w4 = make_float2(w2.x * w2.x - w2.y * w2.y, 2.f * w2.x * w2.y);

    float dd[3];
    #pragma unroll
    for (int c = 0; c < 3; c++) {
        const float2* hb = h + c * 5;
        float acc = hb[0].x;                       // k2=0: w=(1,0)
        acc += hb[1].x * w1.x - hb[1].y * w1.y;
        acc += hb[2].x * w2.x - hb[2].y * w2.y;
        acc += hb[3].x * w3.x - hb[3].y * w3.y;
        acc += hb[4].x * w4.x - hb[4].y * w4.y;
        dd[c] = acc;
    }

    // grid_sample: bilinear, border clamp, align_corners=True -> sample at i - disp
    float fz = fminf(fmaxf((float)i0 - dd[0], 0.f), 31.f);
    float fy = fminf(fmaxf((float)i1 - dd[1], 0.f), 255.f);
    float fx = fminf(fmaxf((float)i2 - dd[2], 0.f), 255.f);
    int z0 = (int)fz, y0 = (int)fy, x0 = (int)fx;
    float wz = fz - (float)z0, wy = fy - (float)y0, wx = fx - (float)x0;
    int z1 = min(z0 + 1, 31), y1 = min(y0 + 1, 255);

    // quads already encode x1 = min(x0+1,255)
    int q00 = z0 * 65536 + y0 * 256 + x0;
    int q01 = z0 * 65536 + y1 * 256 + x0;
    int q10 = z1 * 65536 + y0 * 256 + x0;
    int q11 = z1 * 65536 + y1 * 256 + x0;
    int pix = i0 * 65536 + i1 * 256 + i2;

    float iwx = 1.f - wx, iwy = 1.f - wy, iwz = 1.f - wz;

    uint2 v[24];
    #pragma unroll
    for (int g = 0; g < NPAIR; g++) {
        const uint2* p = d_quads + ((size_t)g << 21);
        v[g*4+0] = __ldg(p + q00);
        v[g*4+1] = __ldg(p + q01);
        v[g*4+2] = __ldg(p + q10);
        v[g*4+3] = __ldg(p + q11);
    }
    #pragma unroll
    for (int g = 0; g < NPAIR; g++) {
        float2 a00 = __half22float2(*reinterpret_cast<__half2*>(&v[g*4+0].x));
        float2 a01 = __half22float2(*reinterpret_cast<__half2*>(&v[g*4+1].x));
        float2 a10 = __half22float2(*reinterpret_cast<__half2*>(&v[g*4+2].x));
        float2 a11 = __half22float2(*reinterpret_cast<__half2*>(&v[g*4+3].x));
        float c00 = a00.x * iwx + a00.y * wx;
        float c01 = a01.x * iwx + a01.y * wx;
        float c10 = a10.x * iwx + a10.y * wx;
        float c11 = a11.x * iwx + a11.y * wx;
        float ra = (c00 * iwy + c01 * wy) * iwz + (c10 * iwy + c11 * wy) * wz;

        float2 b00 = __half22float2(*reinterpret_cast<__half2*>(&v[g*4+0].y));
        float2 b01 = __half22float2(*reinterpret_cast<__half2*>(&v[g*4+1].y));
        float2 b10 = __half22float2(*reinterpret_cast<__half2*>(&v[g*4+2].y));
        float2 b11 = __half22float2(*reinterpret_cast<__half2*>(&v[g*4+3].y));
        c00 = b00.x * iwx + b00.y * wx;
        c01 = b01.x * iwx + b01.y * wx;
        c10 = b10.x * iwx + b10.y * wx;
        c11 = b11.x * iwx + b11.y * wx;
        float rb = (c00 * iwy + c01 * wy) * iwz + (c10 * iwy + c11 * wy) * wz;

        __stcs(out + (size_t)(2 * g) * PIX + pix, ra);
        __stcs(out + (size_t)(2 * g + 1) * PIX + pix, rb);
    }
}

extern "C" void kernel_launch(void* const* d_in, const int* in_sizes, int n_in,
                              void* d_out, int out_size) {
    const float* fr       = (const float*)d_in[0];
    const float* seeds    = (const float*)d_in[1];
    const float* Pk       = (const float*)d_in[2];
    const float* defscale = (const float*)d_in[3];
    const int*   feed_idx = (const int*)d_in[5];
    int fdim = in_sizes[5];

    pack_h_kernel<<<H_BLOCKS + PACK_BLOCKS, 256>>>(fr, seeds, Pk, defscale, feed_idx, fdim);
    dim3 g(256, 32);
    deform_kernel<<<g, 256>>>((float*)d_out);
}

// round 15
// speedup vs baseline: 1.4050x; 1.0733x over previous
#include <cuda_runtime.h>
#include <cuda_fp16.h>

#define NFLAT 1056768   /* 32*256*129 */
#define PLANE_F 33024   /* 256*129 */
#define PIX 2097152     /* 32*256*256 per (b,c) plane */
#define NREAL 25165824  /* 12 * PIX */
#define NPAIR 6         /* plane pairs */
#define PACK_BLOCKS 12288  /* NPAIR*PIX/4/256 */
#define H_BLOCKS 480       /* 15 (c,k2) x 32 i0 */
#define CHUNK 512

__device__ float2  d_H[8192 * 15];     // [i0*256+i1][c*5+k2]
__device__ uint2   d_quads[NPAIR * PIX]; // (pa[x],pa[x+1],pb[x],pb[x+1]) fp16 quads

__device__ __forceinline__ unsigned pk2(float a, float b) {
    __half2 h = __floats2half2_rn(a, b);
    return *reinterpret_cast<unsigned*>(&h);
}

// Blocks [0, H_BLOCKS): fold sparse spectrum into per-row H (staged feed).
// Blocks [H_BLOCKS, ...): pack fr plane-pairs into staggered fp16 quads.
__global__ void __launch_bounds__(256) pack_h_kernel(
        const float* __restrict__ fr,
        const float* __restrict__ seeds,
        const float* __restrict__ Pk,
        const float* __restrict__ defscale,
        const int*  __restrict__ feed_idx,
        int fdim) {
    if (blockIdx.x < H_BLOCKS) {
        __shared__ float2 sW[256];
        __shared__ float sV[CHUNK];
        __shared__ int   sM[CHUNK];
        int tid = threadIdx.x;
        {
            float sn, cs;
            sincospif((float)tid * (1.0f / 128.0f), &sn, &cs);
            sW[tid] = make_float2(cs, sn);
        }
        int ex = blockIdx.x;
        int ck = ex >> 5;            // 0..14 = c*5+k2
        int i0 = ex & 31;
        int i1 = tid;
        int c  = ck / 5, k2 = ck - c * 5;
        float dsc = __ldg(defscale + c);
        const float inv_n = 1.0f / 2097152.0f;    // irfftn normalization
        float ax = 0.f, ay = 0.f;

        for (int base = 0; base < fdim; base += CHUNK) {
            int len = min(CHUNK, fdim - base);
            __syncthreads();
            for (int t = tid; t < len; t += 256) {
                int j = base + t;
                int flat = __ldg(feed_idx + j);
                int part = flat / NFLAT;              // 0 = re, 1 = im
                int r = flat - part * NFLAT;
                int k0 = r / PLANE_F; r -= k0 * PLANE_F;
                int k1 = r / 129;
                int k2e = r - k1 * 129;
                int f0 = (k0 <= 16) ? k0 : k0 - 32;   // |f0| <= 4 (ksq<=16)
                int f1 = (k1 <= 128) ? k1 : k1 - 256; // |f1| <= 4
                float w = (k0 == 0 && k1 == 0 && k2e == 0) ? 1.0f : 2.0f;
                float v = __ldg(Pk + j) * w * inv_n
                        * __ldg(seeds + c * fdim + j) * dsc;
                // part=1 (i * e^{it}) == phase rotation by +64/256 turn
                int tb = (8 * f0 * i0 + 64 * part + 8192) & 255;
                sV[t] = (k2e == k2) ? v : 0.0f;       // mask wrong-k2 entries
                sM[t] = (tb << 8) | (f1 + 4);
            }
            __syncthreads();
            for (int t = 0; t < len; t++) {
                int m = sM[t];
                float v = sV[t];
                int tt = ((m >> 8) + ((m & 15) - 4) * i1) & 255;
                float2 wv = sW[tt];
                ax += v * wv.x;
                ay += v * wv.y;
            }
        }
        d_H[(i0 * 256 + i1) * 15 + ck] = make_float2(ax, ay);
    } else {
        int t = (blockIdx.x - H_BLOCKS) * 256 + threadIdx.x;
        int i = t * 4;                       // pixel index within pair plane * 4
        int g = i >> 21;                     // pair id (PIX = 2^21)
        int pix = i & (PIX - 1);
        const float* pa = fr + (size_t)(2 * g) * PIX;
        const float* pb = pa + PIX;
        float4 fa = __ldcs(reinterpret_cast<const float4*>(pa + pix));
        float4 fb = __ldcs(reinterpret_cast<const float4*>(pb + pix));
        int nn = min(pix + 4, PIX - 1);
        float sa = __ldcs(pa + nn);
        float sb = __ldcs(pb + nn);
        int pos = pix & 255;
        float na = (pos == 252) ? fa.w : sa;   // clamp pair at row end (x=255)
        float nb = (pos == 252) ? fb.w : sb;
        uint4 u0, u1;
        u0.x = pk2(fa.x, fa.y); u0.y = pk2(fb.x, fb.y);
        u0.z = pk2(fa.y, fa.z); u0.w = pk2(fb.y, fb.z);
        u1.x = pk2(fa.z, fa.w); u1.y = pk2(fb.z, fb.w);
        u1.z = pk2(fa.w, na);   u1.w = pk2(fb.w, nb);
        uint4* dst = reinterpret_cast<uint4*>(d_quads + ((size_t)g << 21) + pix);
        dst[0] = u0;
        dst[1] = u1;
    }
}

// Barrier-free, smem-free deform. Reg-lean: per-channel H consumption and
// 2-pair gather chunks so __launch_bounds__(256,8) holds without spills.
__global__ void __launch_bounds__(256, 8) deform_kernel(float* __restrict__ out) {
    int i2 = threadIdx.x;
    int i1 = blockIdx.x;
    int i0 = blockIdx.y;

    float s1, c1;
    sincospif((float)i2 * (1.0f / 128.0f), &s1, &c1);
    float2 w1 = make_float2(c1, s1);
    float2 w2 = make_float2(c1 * c1 - s1 * s1, 2.f * c1 * s1);
    float2 w3 = make_float2(w2.x * w1.x - w2.y * w1.y, w2.x * w1.y + w2.y * w1.x);
    float2 w4 = make_float2(w2.x * w2.x - w2.y * w2.y, 2.f * w2.x * w2.y);

    const float2* Hp = d_H + (i0 * 256 + i1) * 15;
    float dd[3];
    #pragma unroll
    for (int c = 0; c < 3; c++) {
        float2 h0 = __ldg(Hp + c * 5 + 0);
        float2 h1 = __ldg(Hp + c * 5 + 1);
        float2 h2 = __ldg(Hp + c * 5 + 2);
        float2 h3 = __ldg(Hp + c * 5 + 3);
        float2 h4 = __ldg(Hp + c * 5 + 4);
        float acc = h0.x;                          // k2=0: w=(1,0)
        acc += h1.x * w1.x - h1.y * w1.y;
        acc += h2.x * w2.x - h2.y * w2.y;
        acc += h3.x * w3.x - h3.y * w3.y;
        acc += h4.x * w4.x - h4.y * w4.y;
        dd[c] = acc;
    }

    // grid_sample: bilinear, border clamp, align_corners=True -> sample at i - disp
    float fz = fminf(fmaxf((float)i0 - dd[0], 0.f), 31.f);
    float fy = fminf(fmaxf((float)i1 - dd[1], 0.f), 255.f);
    float fx = fminf(fmaxf((float)i2 - dd[2], 0.f), 255.f);
    int z0 = (int)fz, y0 = (int)fy, x0 = (int)fx;
    float wz = fz - (float)z0, wy = fy - (float)y0, wx = fx - (float)x0;
    int z1 = min(z0 + 1, 31), y1 = min(y0 + 1, 255);

    // quads already encode x1 = min(x0+1,255)
    int q00 = z0 * 65536 + y0 * 256 + x0;
    int q01 = z0 * 65536 + y1 * 256 + x0;
    int q10 = z1 * 65536 + y0 * 256 + x0;
    int q11 = z1 * 65536 + y1 * 256 + x0;
    int pix = i0 * 65536 + i1 * 256 + i2;

    float iwx = 1.f - wx, iwy = 1.f - wy, iwz = 1.f - wz;

    #pragma unroll
    for (int gg = 0; gg < 3; gg++) {
        uint2 v[8];
        #pragma unroll
        for (int b = 0; b < 2; b++) {
            const uint2* p = d_quads + ((size_t)(2 * gg + b) << 21);
            v[b*4+0] = __ldg(p + q00);
            v[b*4+1] = __ldg(p + q01);
            v[b*4+2] = __ldg(p + q10);
            v[b*4+3] = __ldg(p + q11);
        }
        #pragma unroll
        for (int b = 0; b < 2; b++) {
            int g = 2 * gg + b;
            float2 a00 = __half22float2(*reinterpret_cast<__half2*>(&v[b*4+0].x));
            float2 a01 = __half22float2(*reinterpret_cast<__half2*>(&v[b*4+1].x));
            float2 a10 = __half22float2(*reinterpret_cast<__half2*>(&v[b*4+2].x));
            float2 a11 = __half22float2(*reinterpret_cast<__half2*>(&v[b*4+3].x));
            float c00 = a00.x * iwx + a00.y * wx;
            float c01 = a01.x * iwx + a01.y * wx;
            float c10 = a10.x * iwx + a10.y * wx;
            float c11 = a11.x * iwx + a11.y * wx;
            float ra = (c00 * iwy + c01 * wy) * iwz + (c10 * iwy + c11 * wy) * wz;

            float2 b00 = __half22float2(*reinterpret_cast<__half2*>(&v[b*4+0].y));
            float2 b01 = __half22float2(*reinterpret_cast<__half2*>(&v[b*4+1].y));
            float2 b10 = __half22float2(*reinterpret_cast<__half2*>(&v[b*4+2].y));
            float2 b11 = __half22float2(*reinterpret_cast<__half2*>(&v[b*4+3].y));
            c00 = b00.x * iwx + b00.y * wx;
            c01 = b01.x * iwx + b01.y * wx;
            c10 = b10.x * iwx + b10.y * wx;
            c11 = b11.x * iwx + b11.y * wx;
            float rb = (c00 * iwy + c01 * wy) * iwz + (c10 * iwy + c11 * wy) * wz;

            __stcs(out + (size_t)(2 * g) * PIX + pix, ra);
            __stcs(out + (size_t)(2 * g + 1) * PIX + pix, rb);
        }
    }
}

extern "C" void kernel_launch(void* const* d_in, const int* in_sizes, int n_in,
                              void* d_out, int out_size) {
    const float* fr       = (const float*)d_in[0];
    const float* seeds    = (const float*)d_in[1];
    const float* Pk       = (const float*)d_in[2];
    const float* defscale = (const float*)d_in[3];
    const int*   feed_idx = (const int*)d_in[5];
    int fdim = in_sizes[5];

    pack_h_kernel<<<H_BLOCKS + PACK_BLOCKS, 256>>>(fr, seeds, Pk, defscale, feed_idx, fdim);
    dim3 g(256, 32);
    deform_kernel<<<g, 256>>>((float*)d_out);
}